// round 9
// baseline (speedup 1.0000x reference)
#include <cuda_runtime.h>
#include <cstdint>

// OverlapPatchEmbed: x (64,3,224,224) fp32 -> out (64,729,3,256) fp32.
// 16x16 patches, stride 8, 27x27 patches per image.
//
// R5 design (resubmit #3 after broker timeouts): occupancy fix over R4's
// smem staging. CTA = one (b, py, c) channel slab (was full 3-channel
// band): smem 46KB -> 15.4KB, so occupancy goes thread-limited (10 CTAs x
// 192thr = 60/64 warps ~ 94%) instead of smem-limited (4 CTAs = 37.5%).
//  - Load: 16 rows x 224 floats, contiguous per row, fully coalesced
//    LDG.128 into smem (pitch 240 floats).
//  - Store: 27 patches x 64 float4 contiguous chunks (1KB each, stride
//    3KB), fully coalesced STG.128 via __stcs (streaming; protects input
//    L2 residency from the 143MB write stream).
//  - Smem gather conflict-free: float4 addr mod 8 = (4*ky + kx4) mod 8
//    covers all 8 phases within each 8-lane group.

static constexpr int B  = 64;
static constexpr int C  = 3;
static constexpr int H  = 224;
static constexpr int W  = 224;
static constexpr int P  = 16;     // patch size
static constexpr int S  = 8;      // stride
static constexpr int N  = 27;     // patches per dim

static constexpr int W_F4     = W / 4;        // 56 float4 per input row
static constexpr int PITCH_F4 = 60;           // 240-float pitch, conflict-free
static constexpr int SMEM_F4  = P * PITCH_F4; // 960 float4 = 15360 B

static constexpr int THREADS  = 192;
static constexpr int LOAD_F4  = P * W_F4;         // 896
static constexpr int STORE_F4 = N * P * P / 4;    // 1728 -> 9 iters exact
static constexpr int LOAD_ITERS  = (LOAD_F4 + THREADS - 1) / THREADS;  // 5 (last partial)
static constexpr int STORE_ITERS = STORE_F4 / THREADS;                 // 9

__global__ __launch_bounds__(THREADS)
void overlap_patch_kernel(const float4* __restrict__ x,
                          float4* __restrict__ out)
{
    __shared__ float4 sm[SMEM_F4];   // 15 KB

    const int tid = threadIdx.x;
    int bx = blockIdx.x;
    const int c  = bx % C;
    bx /= C;
    const int py = bx % N;
    const int b  = bx / N;

    // ---- Load phase: 16 rows x 56 float4 of channel c, rows py*8.. ----
    const int64_t gbase = ((int64_t)(b * C + c) * H + py * S) * W_F4;
    #pragma unroll
    for (int k = 0; k < LOAD_ITERS; k++) {
        int g = tid + k * THREADS;               // [0, 896)
        if (g < LOAD_F4) {
            int row  = g / W_F4;
            int col4 = g - row * W_F4;
            sm[row * PITCH_F4 + col4] = __ldg(&x[gbase + row * W_F4 + col4]);
        }
    }

    __syncthreads();

    // ---- Store phase: 27 patches x 64 float4 each ----
    // out float4 index = ((b*729 + py*27 + px)*3 + c)*64 + within
    const int64_t obase = ((int64_t)(b * (N * N) + py * N) * C + c) * (P * P / 4);

    #pragma unroll
    for (int k = 0; k < STORE_ITERS; k++) {
        int j      = tid + k * THREADS;          // [0, 1728)
        int px     = j >> 6;                     // patch column
        int within = j & 63;                     // float4 within patch
        int kx4    = within & 3;
        int ky     = within >> 2;

        float4 v = sm[ky * PITCH_F4 + px * 2 + kx4];
        __stcs(&out[obase + (int64_t)px * (C * P * P / 4) + within], v);
    }
}

extern "C" void kernel_launch(void* const* d_in, const int* in_sizes, int n_in,
                              void* d_out, int out_size)
{
    const float4* x = (const float4*)d_in[0];
    float4* out = (float4*)d_out;

    overlap_patch_kernel<<<B * N * C, THREADS>>>(x, out);   // 5184 CTAs
}

// round 12
// speedup vs baseline: 1.0218x; 1.0218x over previous
#include <cuda_runtime.h>
#include <cuda_pipeline.h>
#include <cstdint>

// OverlapPatchEmbed: x (64,3,224,224) fp32 -> out (64,729,3,256) fp32.
// 16x16 patches, stride 8, 27x27 patches per image.
//
// R9 design (resubmit #2 after broker timeouts): software pipeline.
// R4 vs R5 proved occupancy irrelevant (24 vs 48 warps/SM, identical
// 28-29us, DRAM stuck ~54%): the limiter is the load-burst -> barrier ->
// store-burst structure exposing full DRAM latency once per slab. Fix:
// CTA = (b, py) band, 3 channel slabs, double-buffered smem with
// cp.async — the load for slab c+1 is in flight while slab c is being
// stored, so the DRAM read stream never stalls behind a barrier.
//  - cp.async 16B (LDGSTS.128): gmem->smem with no register round-trip.
//  - One commit group per iteration (empty group on the last), then
//    wait_prior(1) == "previous slab complete".
//  - Store: 27 patches x 64 float4 contiguous chunks, coalesced __stcs.
//  - Smem gather conflict-free (pitch 240 floats).

static constexpr int B  = 64;
static constexpr int C  = 3;
static constexpr int H  = 224;
static constexpr int W  = 224;
static constexpr int P  = 16;
static constexpr int S  = 8;
static constexpr int N  = 27;

static constexpr int W_F4     = W / 4;          // 56 float4 per input row
static constexpr int PITCH_F4 = 60;             // 240-float pitch, conflict-free
static constexpr int SLAB_F4  = P * PITCH_F4;   // 960 float4 = 15360 B per slab

static constexpr int THREADS     = 192;
static constexpr int LOAD_F4     = P * W_F4;        // 896
static constexpr int STORE_F4    = N * P * P / 4;   // 1728
static constexpr int STORE_ITERS = STORE_F4 / THREADS;  // 9

__global__ __launch_bounds__(THREADS)
void overlap_patch_kernel(const float4* __restrict__ x,
                          float4* __restrict__ out)
{
    __shared__ float4 sm[2][SLAB_F4];   // 30.7 KB

    const int tid = threadIdx.x;
    const int bx  = blockIdx.x;
    const int b   = bx / N;
    const int py  = bx - b * N;

    // Issue cp.async for channel slab c into buffer buf.
    auto issue_slab = [&](int c, int buf) {
        const float4* g = x + ((int64_t)(b * C + c) * H + py * S) * W_F4;
        #pragma unroll
        for (int k = 0; k < 5; k++) {
            int i = tid + k * THREADS;          // [0, 896)
            if (i < LOAD_F4) {
                int row = i / W_F4;
                int col = i - row * W_F4;
                __pipeline_memcpy_async(&sm[buf][row * PITCH_F4 + col],
                                        &g[row * W_F4 + col], 16);
            }
        }
    };

    // Prologue: slab 0 in flight.
    issue_slab(0, 0);
    __pipeline_commit();

    #pragma unroll
    for (int c = 0; c < C; c++) {
        // All reads of sm[(c+1)&1] (from iteration c-1) are done before we
        // overwrite it with the next slab's cp.async.
        __syncthreads();

        if (c + 1 < C) issue_slab(c + 1, (c + 1) & 1);
        __pipeline_commit();              // exactly one group per iter (may be empty)
        __pipeline_wait_prior(1);         // slab c complete (own thread's copies)
        __syncthreads();                  // cross-thread visibility of slab c

        // Store slab c: 27 patches x 64 float4, fully coalesced.
        const int64_t obase = ((int64_t)(b * (N * N) + py * N) * C + c) * (P * P / 4);
        #pragma unroll
        for (int k = 0; k < STORE_ITERS; k++) {
            int j      = tid + k * THREADS;   // [0, 1728)
            int px     = j >> 6;
            int within = j & 63;
            int kx4    = within & 3;
            int ky     = within >> 2;

            float4 v = sm[c & 1][ky * PITCH_F4 + px * 2 + kx4];
            __stcs(&out[obase + (int64_t)px * (C * P * P / 4) + within], v);
        }
    }
}

extern "C" void kernel_launch(void* const* d_in, const int* in_sizes, int n_in,
                              void* d_out, int out_size)
{
    const float4* x = (const float4*)d_in[0];
    float4* out = (float4*)d_out;

    overlap_patch_kernel<<<B * N, THREADS>>>(x, out);   // 1728 CTAs, 3 slabs each
}

// round 13
// speedup vs baseline: 1.0718x; 1.0490x over previous
#include <cuda_runtime.h>
#include <cuda_pipeline.h>
#include <cstdint>

// OverlapPatchEmbed: x (64,3,224,224) fp32 -> out (64,729,3,256) fp32.
// 16x16 patches, stride 8, 27x27 patches per image.
//
// R13: LTS-traffic reduction. All prior variants converge at ~4.4TB/s
// with no pipe >57% -> the binding resource is L2 slice (LTS) throughput
// (~400MB of L2-side traffic per launch hits the measured ~6300 B/cyc
// cap). The only reducible term is the 2x input read overlap between
// vertically adjacent py bands. CTA = (b, c, group of 3 py bands): loads
// 32 rows ONCE (amp 1.33x instead of 2x), stores 3 bands of 27 patches.
// Also: one __syncthreads per CTA instead of three.
//  - Load: 32 rows x 56 float4, cp.async, coalesced; smem pitch 60 f4.
//  - Store: 81 patches x 64 float4 contiguous chunks, coalesced __stcs.
//  - Smem gather conflict-free: (4*ky+kx4) mod 8 distinct per 8-lane phase
//    (pitch 60 f4: 60 mod 8 = 4).

static constexpr int B  = 64;
static constexpr int C  = 3;
static constexpr int H  = 224;
static constexpr int W  = 224;
static constexpr int P  = 16;
static constexpr int S  = 8;
static constexpr int N  = 27;
static constexpr int G  = 3;              // py bands per CTA
static constexpr int NG = N / G;          // 9 groups

static constexpr int ROWS_PER_CTA = G * S + S;   // 32 rows (16 + 8 + 8)
static constexpr int W_F4     = W / 4;           // 56
static constexpr int PITCH_F4 = 60;              // conflict-free pitch
static constexpr int SMEM_F4  = ROWS_PER_CTA * PITCH_F4;  // 1920 f4 = 30720 B

static constexpr int THREADS  = 192;
static constexpr int LOAD_F4  = ROWS_PER_CTA * W_F4;      // 1792
static constexpr int LOAD_ITERS = (LOAD_F4 + THREADS - 1) / THREADS;   // 10 (last partial)
static constexpr int BAND_F4  = N * P * P / 4;            // 1728 per band
static constexpr int STORE_ITERS = BAND_F4 / THREADS;     // 9 exact

__global__ __launch_bounds__(THREADS)
void overlap_patch_kernel(const float4* __restrict__ x,
                          float4* __restrict__ out)
{
    __shared__ float4 sm[SMEM_F4];   // 30.7 KB

    const int tid = threadIdx.x;
    int bx = blockIdx.x;
    const int c  = bx % C;
    bx /= C;
    const int gy = bx % NG;          // vertical group
    const int b  = bx / NG;

    // ---- Load 32 rows of channel c starting at row gy*24 ----
    const float4* g = x + ((int64_t)(b * C + c) * H + gy * (G * S)) * W_F4;
    #pragma unroll
    for (int k = 0; k < LOAD_ITERS; k++) {
        int i = tid + k * THREADS;              // [0, 1792)
        if (i < LOAD_F4) {
            int row = i / W_F4;
            int col = i - row * W_F4;
            __pipeline_memcpy_async(&sm[row * PITCH_F4 + col],
                                    &g[row * W_F4 + col], 16);
        }
    }
    __pipeline_commit();
    __pipeline_wait_prior(0);
    __syncthreads();                 // the ONLY barrier in this CTA

    // ---- Store 3 bands x 27 patches x 64 float4 ----
    #pragma unroll
    for (int j = 0; j < G; j++) {
        const int py = gy * G + j;
        const int64_t obase = ((int64_t)(b * (N * N) + py * N) * C + c) * (P * P / 4);
        const int rbase = j * S;     // smem row offset for this band

        #pragma unroll
        for (int k = 0; k < STORE_ITERS; k++) {
            int idx    = tid + k * THREADS;     // [0, 1728)
            int px     = idx >> 6;
            int within = idx & 63;
            int kx4    = within & 3;
            int ky     = within >> 2;

            float4 v = sm[(rbase + ky) * PITCH_F4 + px * 2 + kx4];
            __stcs(&out[obase + (int64_t)px * (C * P * P / 4) + within], v);
        }
    }
}

extern "C" void kernel_launch(void* const* d_in, const int* in_sizes, int n_in,
                              void* d_out, int out_size)
{
    const float4* x = (const float4*)d_in[0];
    float4* out = (float4*)d_out;

    overlap_patch_kernel<<<B * C * NG, THREADS>>>(x, out);   // 1728 CTAs
}